// round 10
// baseline (speedup 1.0000x reference)
#include <cuda_runtime.h>

#define TPB 64
#define NSWEEP 6

// ---------------------------------------------------------------------------
// Compile-time index helpers (all call sites have constant args -> fold away).
// ---------------------------------------------------------------------------

// Lexicographic index of combination (a<b<c) out of C(7,3)=35.
__device__ __forceinline__ int tri_idx(int a, int b, int c) {
    int idx = 0;
#pragma unroll
    for (int x = 0; x < 7; ++x)
        if (x < a) idx += (6 - x) * (5 - x) / 2;
    idx += ((b - a - 1) * (12 - a - b)) / 2;
    idx += (c - b - 1);
    return idx;
}

// pf(a, m, n) with m<n, a distinct from both: phi index + sign (+-1).
__device__ __forceinline__ void pf_ref(int a, int m, int n, int &idx, float &sg) {
    if (a < m)      { idx = tri_idx(a, m, n); sg =  1.0f; }
    else if (a < n) { idx = tri_idx(m, a, n); sg = -1.0f; }
    else            { idx = tri_idx(m, n, a); sg =  1.0f; }
}

// Sign of the permutation (k,l,m,n,p,q,r) of (0..6).
__device__ __forceinline__ float eps_sign7(int k, int l, int m, int n,
                                           int p, int q, int r) {
    int arr[7] = {k, l, m, n, p, q, r};
    int inv = 0;
#pragma unroll
    for (int x = 0; x < 7; ++x)
#pragma unroll
        for (int y = x + 1; y < 7; ++y)
            inv += (arr[x] > arr[y]) ? 1 : 0;
    return (inv & 1) ? -1.0f : 1.0f;
}

// Upper-triangle packed index for 7x7 symmetric, requires i<=j.
__device__ __forceinline__ int ui(int i, int j) {
    return 7 * i - (i * (i - 1)) / 2 + (j - i);
}
__device__ __forceinline__ int uis(int i, int j) {   // symmetric access
    return (i <= j) ? ui(i, j) : ui(j, i);
}

// ---------------------------------------------------------------------------
// Kahan-compensated fp32 accumulator. True value = s - c.
// ---------------------------------------------------------------------------
struct KF { float s, c; };

__device__ __forceinline__ void kacc(KF &a, float m, float e1) {
    const float y  = m - a.c;
    const float t2 = a.s + y;
    a.c = ((t2 - a.s) - y) - e1;
    a.s = t2;
}

// ---------------------------------------------------------------------------
// Kernel: contraction = one thread per element (compensated fp32, proven);
// Jacobi = even lanes run TWO interleaved problems (ILP-2 on the serial
// MUFU scalar chains), exact R8 cyclic ordering per problem.
// ---------------------------------------------------------------------------
__global__ void __launch_bounds__(TPB)
positivity_kernel(const float* __restrict__ phi, float* __restrict__ out, int n)
{
    __shared__ float sphi[TPB * 35];

    const int base = blockIdx.x * TPB;
    {   // coalesced staging of this block's phi rows
        int limit = (n - base) * 35;
        if (limit > TPB * 35) limit = TPB * 35;
        for (int idx = threadIdx.x; idx < limit; idx += TPB)
            sphi[idx] = phi[(long long)base * 35 + idx];
    }
    __syncthreads();

    const int b = base + threadIdx.x;
    if (b >= n) return;   // n is a multiple of TPB in practice; full warps

    float P[35];
#pragma unroll
    for (int t = 0; t < 35; ++t) P[t] = sphi[threadIdx.x * 35 + t];

    // -----------------------------------------------------------------
    // Compensated contraction (unchanged from R8 -- accuracy anchor).
    // -----------------------------------------------------------------
    KF B[28];
#pragma unroll
    for (int z = 0; z < 28; ++z) { B[z].s = 0.0f; B[z].c = 0.0f; }

#pragma unroll
    for (int k = 0; k < 7; ++k) {
#pragma unroll
        for (int l = k + 1; l < 7; ++l) {
            KF t[7];
#pragma unroll
            for (int j = 0; j < 7; ++j) { t[j].s = 0.0f; t[j].c = 0.0f; }

#pragma unroll
            for (int m = 0; m < 7; ++m) {
#pragma unroll
                for (int nn = m + 1; nn < 7; ++nn) {
                    if (m == k || m == l || nn == k || nn == l) continue;
                    int p = -1, q = -1, r = -1;
#pragma unroll
                    for (int x = 0; x < 7; ++x) {
                        if (x == k || x == l || x == m || x == nn) continue;
                        if (p < 0) p = x;
                        else if (q < 0) q = x;
                        else r = x;
                    }
                    const float es = eps_sign7(k, l, m, nn, p, q, r);
                    const float Cv = es * P[tri_idx(p, q, r)];
#pragma unroll
                    for (int j = 0; j < 7; ++j) {
                        if (j == m || j == nn) continue;
                        int pi; float ps;
                        pf_ref(j, m, nn, pi, ps);
                        const float x1 = (ps > 0.0f) ? Cv : -Cv;
                        const float mprod = x1 * P[pi];
                        const float eprod = fmaf(x1, P[pi], -mprod);
                        kacc(t[j], mprod, eprod);
                    }
                }
            }
#pragma unroll
            for (int i = 0; i < 7; ++i) {
                if (i == k || i == l) continue;
                int ai; float as;
                pf_ref(i, k, l, ai, as);
                const float av = (as > 0.0f) ? P[ai] : -P[ai];
#pragma unroll
                for (int j = i; j < 7; ++j) {
                    const float mprod = av * t[j].s;
                    float e = fmaf(av, t[j].s, -mprod);
                    e = fmaf(av, -t[j].c, e);
                    kacc(B[ui(i, j)], mprod, e);
                }
            }
        }
    }

    // Finalize to plain fp32 matrix.
    float myA[28];
#pragma unroll
    for (int z = 0; z < 28; ++z) myA[z] = (B[z].s - B[z].c) * (1.0f / 6.0f);

    // -----------------------------------------------------------------
    // Pair up: even lane grabs odd neighbor's matrix, runs 2 problems.
    // (Both lanes execute the shuffles; odd lanes then go idle.)
    // -----------------------------------------------------------------
    float A2[2][28];
#pragma unroll
    for (int z = 0; z < 28; ++z) {
        A2[0][z] = myA[z];
        A2[1][z] = __shfl_down_sync(0xFFFFFFFFu, myA[z], 1);
    }

    if (threadIdx.x & 1) return;   // odd lanes done (their data moved over)

    // -----------------------------------------------------------------
    // Cyclic Jacobi (R8 ordering), 2 independent problems interleaved.
    // Scalars: t = 2*apq / (d + copysign(sqrt(d^2+4apq^2), d)), the
    // minimal-|t| root -- algebraically identical to the theta form.
    // -----------------------------------------------------------------
#pragma unroll 1
    for (int sweep = 0; sweep < NSWEEP; ++sweep) {
#pragma unroll
        for (int p = 0; p < 7; ++p) {
#pragma unroll
            for (int q = p + 1; q < 7; ++q) {
#pragma unroll
                for (int e = 0; e < 2; ++e) {
                    float *A = A2[e];

                    const float apq = A[ui(p, q)];
                    const float d   = A[ui(q, q)] - A[ui(p, p)];
                    const float ap2 = apq + apq;
                    const float u   = fmaf(d, d, ap2 * ap2);
                    const float rt  = u * rsqrtf(u);           // sqrt(u)
                    const float den = d + copysignf(rt, d);
                    float tt = __fdividef(ap2, den);
                    tt = (u < 1e-37f) ? 0.0f : tt;             // 0/0+denorm guard

                    const float c  = rsqrtf(fmaf(tt, tt, 1.0f));
                    const float s  = tt * c;
                    const float ns = -s;

                    A[ui(p, p)] = fmaf(-tt, apq, A[ui(p, p)]);
                    A[ui(q, q)] = fmaf( tt, apq, A[ui(q, q)]);
                    A[ui(p, q)] = 0.0f;

#pragma unroll
                    for (int k2 = 0; k2 < 7; ++k2) {
                        if (k2 == p || k2 == q) continue;
                        const float akp = A[uis(k2, p)];
                        const float akq = A[uis(k2, q)];
                        A[uis(k2, p)] = fmaf(ns, akq, c * akp);
                        A[uis(k2, q)] = fmaf(s,  akp, c * akq);
                    }
                }
            }
        }
    }

    // Tail for both problems; even lane stores results for (b, b+1).
    float res[2];
#pragma unroll
    for (int e = 0; e < 2; ++e) {
        float *A = A2[e];
        float det = 1.0f;
#pragma unroll
        for (int i = 0; i < 7; ++i) det *= A[ui(i, i)];
        const float adet  = fabsf(det) + 1e-12f;
        const float inv_s = exp2f(log2f(adet) * (-1.0f / 9.0f));

        float acc = 0.0f;
#pragma unroll
        for (int i = 0; i < 7; ++i)
            acc += fmaxf(0.0f, fmaf(-A[ui(i, i)], inv_s, 1e-6f));
        res[e] = acc;
    }

    if (b + 1 < n) {
        *reinterpret_cast<float2*>(out + b) = make_float2(res[0], res[1]);
    } else {
        out[b] = res[0];
    }
}

// ---------------------------------------------------------------------------
extern "C" void kernel_launch(void* const* d_in, const int* in_sizes, int n_in,
                              void* d_out, int out_size)
{
    const float* phi = (const float*)d_in[0];
    float* out = (float*)d_out;
    const int n = in_sizes[0] / 35;   // batch count
    const int blocks = (n + TPB - 1) / TPB;
    positivity_kernel<<<blocks, TPB>>>(phi, out, n);
}

// round 12
// speedup vs baseline: 1.2252x; 1.2252x over previous
#include <cuda_runtime.h>

#define TPB 64
#define NSWEEP 5

// ---------------------------------------------------------------------------
// Compile-time index helpers (all call sites have constant args -> fold away).
// ---------------------------------------------------------------------------

// Lexicographic index of combination (a<b<c) out of C(7,3)=35.
__device__ __forceinline__ int tri_idx(int a, int b, int c) {
    int idx = 0;
#pragma unroll
    for (int x = 0; x < 7; ++x)
        if (x < a) idx += (6 - x) * (5 - x) / 2;
    idx += ((b - a - 1) * (12 - a - b)) / 2;
    idx += (c - b - 1);
    return idx;
}

// pf(a, m, n) with m<n, a distinct from both: phi index + sign (+-1).
__device__ __forceinline__ void pf_ref(int a, int m, int n, int &idx, float &sg) {
    if (a < m)      { idx = tri_idx(a, m, n); sg =  1.0f; }
    else if (a < n) { idx = tri_idx(m, a, n); sg = -1.0f; }
    else            { idx = tri_idx(m, n, a); sg =  1.0f; }
}

// Sign of the permutation (k,l,m,n,p,q,r) of (0..6).
__device__ __forceinline__ float eps_sign7(int k, int l, int m, int n,
                                           int p, int q, int r) {
    int arr[7] = {k, l, m, n, p, q, r};
    int inv = 0;
#pragma unroll
    for (int x = 0; x < 7; ++x)
#pragma unroll
        for (int y = x + 1; y < 7; ++y)
            inv += (arr[x] > arr[y]) ? 1 : 0;
    return (inv & 1) ? -1.0f : 1.0f;
}

// Upper-triangle packed index for 7x7 symmetric, requires i<=j.
__device__ __forceinline__ int ui(int i, int j) {
    return 7 * i - (i * (i - 1)) / 2 + (j - i);
}
__device__ __forceinline__ int uis(int i, int j) {   // symmetric access
    return (i <= j) ? ui(i, j) : ui(j, i);
}

// ---------------------------------------------------------------------------
// Kahan-compensated fp32 accumulator. True value = s - c.
// kacc adds a term given as (m, e1) where the true term is m + e1.
// ---------------------------------------------------------------------------
struct KF { float s, c; };

__device__ __forceinline__ void kacc(KF &a, float m, float e1) {
    const float y  = m - a.c;
    const float t2 = a.s + y;
    a.c = ((t2 - a.s) - y) - e1;
    a.s = t2;
}

// ---------------------------------------------------------------------------
// Kernel: one thread per batch element. Compensated fp32 contraction
// (accuracy anchor, unchanged from R8) + cyclic fp32 Jacobi with the
// short rotation-scalar chain (validated in R10), 5 sweeps.
// ---------------------------------------------------------------------------
__global__ void __launch_bounds__(TPB)
positivity_kernel(const float* __restrict__ phi, float* __restrict__ out, int n)
{
    __shared__ float sphi[TPB * 35];

    const int base = blockIdx.x * TPB;
    {   // coalesced staging of this block's phi rows
        int limit = (n - base) * 35;
        if (limit > TPB * 35) limit = TPB * 35;
        for (int idx = threadIdx.x; idx < limit; idx += TPB)
            sphi[idx] = phi[(long long)base * 35 + idx];
    }
    __syncthreads();

    const int b = base + threadIdx.x;
    if (b >= n) return;

    float P[35];
#pragma unroll
    for (int t = 0; t < 35; ++t) P[t] = sphi[threadIdx.x * 35 + t];

    // -----------------------------------------------------------------
    // Compensated contraction (R8, proven at 1.57e-4).
    // B[i<=j] = (1/6) * Sum_{k<l} pf(i,k,l) *
    //      Sum_{m<n in comp(k,l)} eps(k,l,m,n,p,q,r)*P[pqr]*pf(j,m,n)
    // -----------------------------------------------------------------
    KF B[28];
#pragma unroll
    for (int z = 0; z < 28; ++z) { B[z].s = 0.0f; B[z].c = 0.0f; }

#pragma unroll
    for (int k = 0; k < 7; ++k) {
#pragma unroll
        for (int l = k + 1; l < 7; ++l) {
            KF t[7];
#pragma unroll
            for (int j = 0; j < 7; ++j) { t[j].s = 0.0f; t[j].c = 0.0f; }

#pragma unroll
            for (int m = 0; m < 7; ++m) {
#pragma unroll
                for (int nn = m + 1; nn < 7; ++nn) {
                    if (m == k || m == l || nn == k || nn == l) continue;
                    int p = -1, q = -1, r = -1;
#pragma unroll
                    for (int x = 0; x < 7; ++x) {
                        if (x == k || x == l || x == m || x == nn) continue;
                        if (p < 0) p = x;
                        else if (q < 0) q = x;
                        else r = x;
                    }
                    const float es = eps_sign7(k, l, m, nn, p, q, r);
                    const float Cv = es * P[tri_idx(p, q, r)];
#pragma unroll
                    for (int j = 0; j < 7; ++j) {
                        if (j == m || j == nn) continue;
                        int pi; float ps;
                        pf_ref(j, m, nn, pi, ps);
                        const float x1 = (ps > 0.0f) ? Cv : -Cv;
                        const float mprod = x1 * P[pi];
                        const float eprod = fmaf(x1, P[pi], -mprod);
                        kacc(t[j], mprod, eprod);
                    }
                }
            }
#pragma unroll
            for (int i = 0; i < 7; ++i) {
                if (i == k || i == l) continue;
                int ai; float as;
                pf_ref(i, k, l, ai, as);
                const float av = (as > 0.0f) ? P[ai] : -P[ai];
#pragma unroll
                for (int j = i; j < 7; ++j) {
                    const float mprod = av * t[j].s;
                    float e = fmaf(av, t[j].s, -mprod);
                    e = fmaf(av, -t[j].c, e);
                    kacc(B[ui(i, j)], mprod, e);
                }
            }
        }
    }

    // Finalize: A = (B.s - B.c) / 6.
    float A[28];
#pragma unroll
    for (int z = 0; z < 28; ++z) A[z] = (B[z].s - B[z].c) * (1.0f / 6.0f);

    // -----------------------------------------------------------------
    // Cyclic Jacobi (row order p<q), every lane its own problem.
    // Short scalar chain: t = 2*apq/(d + copysign(sqrt(d^2+4apq^2), d))
    // = the minimal-|t| root (identical to the theta form).
    // -----------------------------------------------------------------
#pragma unroll 1
    for (int sweep = 0; sweep < NSWEEP; ++sweep) {
#pragma unroll
        for (int p = 0; p < 7; ++p) {
#pragma unroll
            for (int q = p + 1; q < 7; ++q) {
                const float apq = A[ui(p, q)];
                const float d   = A[ui(q, q)] - A[ui(p, p)];
                const float ap2 = apq + apq;
                const float u   = fmaf(d, d, ap2 * ap2);
                const float rt  = u * rsqrtf(u);            // sqrt(u)
                const float den = d + copysignf(rt, d);
                float tt = __fdividef(ap2, den);
                tt = (u < 1e-37f) ? 0.0f : tt;              // 0/0 + denorm guard

                const float c  = rsqrtf(fmaf(tt, tt, 1.0f));
                const float s  = tt * c;
                const float ns = -s;

                A[ui(p, p)] = fmaf(-tt, apq, A[ui(p, p)]);
                A[ui(q, q)] = fmaf( tt, apq, A[ui(q, q)]);
                A[ui(p, q)] = 0.0f;

#pragma unroll
                for (int k2 = 0; k2 < 7; ++k2) {
                    if (k2 == p || k2 == q) continue;
                    const float akp = A[uis(k2, p)];
                    const float akq = A[uis(k2, q)];
                    A[uis(k2, p)] = fmaf(ns, akq, c * akp);
                    A[uis(k2, q)] = fmaf(s,  akp, c * akq);
                }
            }
        }
    }

    // det = product of eigenvalues; inv_s = (|det|+1e-12)^(-1/9).
    float det = 1.0f;
#pragma unroll
    for (int i = 0; i < 7; ++i) det *= A[ui(i, i)];
    const float adet  = fabsf(det) + 1e-12f;
    const float inv_s = exp2f(log2f(adet) * (-1.0f / 9.0f));

    // out = sum relu(EPS - lambda_i / s)
    float acc = 0.0f;
#pragma unroll
    for (int i = 0; i < 7; ++i)
        acc += fmaxf(0.0f, fmaf(-A[ui(i, i)], inv_s, 1e-6f));

    out[b] = acc;
}

// ---------------------------------------------------------------------------
extern "C" void kernel_launch(void* const* d_in, const int* in_sizes, int n_in,
                              void* d_out, int out_size)
{
    const float* phi = (const float*)d_in[0];
    float* out = (float*)d_out;
    const int n = in_sizes[0] / 35;   // batch count
    const int blocks = (n + TPB - 1) / TPB;
    positivity_kernel<<<blocks, TPB>>>(phi, out, n);
}

// round 13
// speedup vs baseline: 1.3934x; 1.1373x over previous
#include <cuda_runtime.h>

#define TPB 128          // 2 threads per element, 64 elements per block
#define ELEMS 64
#define NSWEEP 5

// ---------------------------------------------------------------------------
// Compile-time index helpers (all call sites have constant args -> fold away).
// ---------------------------------------------------------------------------

// Lexicographic index of combination (a<b<c) out of C(7,3)=35.
__device__ __forceinline__ int tri_idx(int a, int b, int c) {
    int idx = 0;
#pragma unroll
    for (int x = 0; x < 7; ++x)
        if (x < a) idx += (6 - x) * (5 - x) / 2;
    idx += ((b - a - 1) * (12 - a - b)) / 2;
    idx += (c - b - 1);
    return idx;
}

// pf(a, m, n) with m<n, a distinct from both: phi index + sign (+-1).
__device__ __forceinline__ void pf_ref(int a, int m, int n, int &idx, float &sg) {
    if (a < m)      { idx = tri_idx(a, m, n); sg =  1.0f; }
    else if (a < n) { idx = tri_idx(m, a, n); sg = -1.0f; }
    else            { idx = tri_idx(m, n, a); sg =  1.0f; }
}

// Sign of the permutation (k,l,m,n,p,q,r) of (0..6).
__device__ __forceinline__ float eps_sign7(int k, int l, int m, int n,
                                           int p, int q, int r) {
    int arr[7] = {k, l, m, n, p, q, r};
    int inv = 0;
#pragma unroll
    for (int x = 0; x < 7; ++x)
#pragma unroll
        for (int y = x + 1; y < 7; ++y)
            inv += (arr[x] > arr[y]) ? 1 : 0;
    return (inv & 1) ? -1.0f : 1.0f;
}

// Upper-triangle packed index for 7x7 symmetric, requires i<=j.
__device__ __forceinline__ int ui(int i, int j) {
    return 7 * i - (i * (i - 1)) / 2 + (j - i);
}
__device__ __forceinline__ int uis(int i, int j) {   // symmetric access
    return (i <= j) ? ui(i, j) : ui(j, i);
}

// Pair index of (k,l), k<l, within the 21 pairs (compile-time).
__device__ __forceinline__ int pair_idx(int k, int l) {
    return 6 * k - (k * (k - 1)) / 2 + (l - k - 1);
}

// ---------------------------------------------------------------------------
// Kahan-compensated fp32 accumulator. True value = s - c.
// ---------------------------------------------------------------------------
struct KF { float s, c; };

__device__ __forceinline__ void kacc(KF &a, float m, float e1) {
    const float y  = m - a.c;
    const float t2 = a.s + y;
    a.c = ((t2 - a.s) - y) - e1;
    a.s = t2;
}

// ---------------------------------------------------------------------------
// Half-contraction: processes (k,l) pairs with pair_idx % 2 == HALF.
// Writes 28 compensated partials (s - c) to out28. Filter folds at
// compile time (HALF is a template arg, loops fully unrolled).
// ---------------------------------------------------------------------------
template <int HALF>
__device__ __forceinline__ void contract_half(const float *P, float *out28) {
    KF B[28];
#pragma unroll
    for (int z = 0; z < 28; ++z) { B[z].s = 0.0f; B[z].c = 0.0f; }

#pragma unroll
    for (int k = 0; k < 7; ++k) {
#pragma unroll
        for (int l = k + 1; l < 7; ++l) {
            if ((pair_idx(k, l) & 1) != HALF) continue;   // compile-time

            KF t[7];
#pragma unroll
            for (int j = 0; j < 7; ++j) { t[j].s = 0.0f; t[j].c = 0.0f; }

#pragma unroll
            for (int m = 0; m < 7; ++m) {
#pragma unroll
                for (int nn = m + 1; nn < 7; ++nn) {
                    if (m == k || m == l || nn == k || nn == l) continue;
                    int p = -1, q = -1, r = -1;
#pragma unroll
                    for (int x = 0; x < 7; ++x) {
                        if (x == k || x == l || x == m || x == nn) continue;
                        if (p < 0) p = x;
                        else if (q < 0) q = x;
                        else r = x;
                    }
                    const float es = eps_sign7(k, l, m, nn, p, q, r);
                    const float Cv = es * P[tri_idx(p, q, r)];
#pragma unroll
                    for (int j = 0; j < 7; ++j) {
                        if (j == m || j == nn) continue;
                        int pi; float ps;
                        pf_ref(j, m, nn, pi, ps);
                        const float x1 = (ps > 0.0f) ? Cv : -Cv;
                        const float mprod = x1 * P[pi];
                        const float eprod = fmaf(x1, P[pi], -mprod);
                        kacc(t[j], mprod, eprod);
                    }
                }
            }
#pragma unroll
            for (int i = 0; i < 7; ++i) {
                if (i == k || i == l) continue;
                int ai; float as;
                pf_ref(i, k, l, ai, as);
                const float av = (as > 0.0f) ? P[ai] : -P[ai];
#pragma unroll
                for (int j = i; j < 7; ++j) {
                    const float mprod = av * t[j].s;
                    float e = fmaf(av, t[j].s, -mprod);
                    e = fmaf(av, -t[j].c, e);
                    kacc(B[ui(i, j)], mprod, e);
                }
            }
        }
    }

#pragma unroll
    for (int z = 0; z < 28; ++z) out28[z] = B[z].s - B[z].c;
}

// ---------------------------------------------------------------------------
// Kernel: 2 threads per element. Warp-uniform contraction split (lower
// warps = even pairs, upper warps = odd pairs), smem merge, Jacobi on
// the lower half. launch_bounds(128,4) keeps 512 blocks in ONE wave.
// ---------------------------------------------------------------------------
__global__ void __launch_bounds__(TPB, 4)
positivity_kernel(const float* __restrict__ phi, float* __restrict__ out, int n)
{
    __shared__ float sphi[ELEMS * 35];
    __shared__ float spart[ELEMS * 29];   // stride 29: conflict-free merge

    const int tid = threadIdx.x;
    const int base = blockIdx.x * ELEMS;
    {   // coalesced staging of this block's phi rows
        int limit = (n - base) * 35;
        if (limit > ELEMS * 35) limit = ELEMS * 35;
        for (int idx = tid; idx < limit; idx += TPB)
            sphi[idx] = phi[(long long)base * 35 + idx];
    }
    __syncthreads();

    const int e_local = (tid < ELEMS) ? tid : (tid - ELEMS);
    const int b = base + e_local;

    float P[35];
#pragma unroll
    for (int t = 0; t < 35; ++t) P[t] = sphi[e_local * 35 + t];

    float half28[28];
    if (tid < ELEMS) contract_half<0>(P, half28);
    else             contract_half<1>(P, half28);

    // Upper half publishes its partial; lower half merges.
    if (tid >= ELEMS) {
#pragma unroll
        for (int z = 0; z < 28; ++z) spart[e_local * 29 + z] = half28[z];
    }
    __syncthreads();
    if (tid >= ELEMS) return;   // upper warps done

    float A[28];
#pragma unroll
    for (int z = 0; z < 28; ++z)
        A[z] = (half28[z] + spart[e_local * 29 + z]) * (1.0f / 6.0f);

    if (b >= n) return;

    // -----------------------------------------------------------------
    // Cyclic Jacobi (row order p<q), short scalar chain, 5 sweeps
    // (identical to R12, validated at 2.83e-4).
    // -----------------------------------------------------------------
#pragma unroll 1
    for (int sweep = 0; sweep < NSWEEP; ++sweep) {
#pragma unroll
        for (int p = 0; p < 7; ++p) {
#pragma unroll
            for (int q = p + 1; q < 7; ++q) {
                const float apq = A[ui(p, q)];
                const float d   = A[ui(q, q)] - A[ui(p, p)];
                const float ap2 = apq + apq;
                const float u   = fmaf(d, d, ap2 * ap2);
                const float rt  = u * rsqrtf(u);            // sqrt(u)
                const float den = d + copysignf(rt, d);
                float tt = __fdividef(ap2, den);
                tt = (u < 1e-37f) ? 0.0f : tt;              // 0/0 + denorm guard

                const float c  = rsqrtf(fmaf(tt, tt, 1.0f));
                const float s  = tt * c;
                const float ns = -s;

                A[ui(p, p)] = fmaf(-tt, apq, A[ui(p, p)]);
                A[ui(q, q)] = fmaf( tt, apq, A[ui(q, q)]);
                A[ui(p, q)] = 0.0f;

#pragma unroll
                for (int k2 = 0; k2 < 7; ++k2) {
                    if (k2 == p || k2 == q) continue;
                    const float akp = A[uis(k2, p)];
                    const float akq = A[uis(k2, q)];
                    A[uis(k2, p)] = fmaf(ns, akq, c * akp);
                    A[uis(k2, q)] = fmaf(s,  akp, c * akq);
                }
            }
        }
    }

    // det = product of eigenvalues; inv_s = (|det|+1e-12)^(-1/9).
    float det = 1.0f;
#pragma unroll
    for (int i = 0; i < 7; ++i) det *= A[ui(i, i)];
    const float adet  = fabsf(det) + 1e-12f;
    const float inv_s = exp2f(log2f(adet) * (-1.0f / 9.0f));

    // out = sum relu(EPS - lambda_i / s)
    float acc = 0.0f;
#pragma unroll
    for (int i = 0; i < 7; ++i)
        acc += fmaxf(0.0f, fmaf(-A[ui(i, i)], inv_s, 1e-6f));

    out[b] = acc;
}

// ---------------------------------------------------------------------------
extern "C" void kernel_launch(void* const* d_in, const int* in_sizes, int n_in,
                              void* d_out, int out_size)
{
    const float* phi = (const float*)d_in[0];
    float* out = (float*)d_out;
    const int n = in_sizes[0] / 35;   // batch count
    const int blocks = (n + ELEMS - 1) / ELEMS;
    positivity_kernel<<<blocks, TPB>>>(phi, out, n);
}